// round 1
// baseline (speedup 1.0000x reference)
#include <cuda_runtime.h>
#include <cuda_bf16.h>
#include <cstdint>

// Problem constants (match reference)
#define MAX_NODES 100000
#define MAX_EDGES 1600000
#define D 64

// ---------------- scratch (device globals; no allocation allowed) ----------------
__device__ int   g_counts[MAX_NODES + 1];
__device__ int   g_cursor[MAX_NODES + 1];
__device__ int   g_offsets[MAX_NODES + 1];
__device__ float g_invdeg[MAX_NODES];
__device__ int   g_nbr[MAX_EDGES];
__device__ float g_agg[(size_t)MAX_NODES * D];   // h_neigh (pre-scaled by 1/deg)
__device__ float g_h1[(size_t)MAX_NODES * D];    // layer-1 activations

// ---------------- CSR build ----------------
__global__ void zero_counts_kernel(int n_nodes) {
    int i = blockIdx.x * blockDim.x + threadIdx.x;
    if (i < n_nodes) g_counts[i] = 0;
}

__global__ void hist_kernel(const int* __restrict__ edge_dst, int n_edges) {
    int i = blockIdx.x * blockDim.x + threadIdx.x;
    if (i < n_edges) atomicAdd(&g_counts[edge_dst[i]], 1);
}

// single-block exclusive scan over counts -> offsets, cursor, invdeg
__global__ void scan_kernel(int n_nodes) {
    __shared__ int ssum[1024];
    int t = threadIdx.x;
    int chunk = (n_nodes + 1023) >> 10;
    int beg = t * chunk;
    int end = min(beg + chunk, n_nodes);
    int s = 0;
    for (int i = beg; i < end; ++i) s += g_counts[i];
    ssum[t] = s;
    __syncthreads();
    // Hillis-Steele inclusive scan
    for (int off = 1; off < 1024; off <<= 1) {
        int v = (t >= off) ? ssum[t - off] : 0;
        __syncthreads();
        ssum[t] += v;
        __syncthreads();
    }
    int run = (t == 0) ? 0 : ssum[t - 1];
    for (int i = beg; i < end; ++i) {
        int c = g_counts[i];
        g_offsets[i] = run;
        g_cursor[i]  = run;
        g_invdeg[i]  = 1.0f / fmaxf((float)c, 1.0f);
        run += c;
    }
    if (t == 1023) g_offsets[n_nodes] = ssum[1023];
}

__global__ void scatter_kernel(const int* __restrict__ edge_src,
                               const int* __restrict__ edge_dst, int n_edges) {
    int i = blockIdx.x * blockDim.x + threadIdx.x;
    if (i < n_edges) {
        int p = atomicAdd(&g_cursor[edge_dst[i]], 1);
        g_nbr[p] = edge_src[i];
    }
}

// ---------------- aggregation: warp per node, mean of neighbor rows ----------------
// use_h1=0: input = xin (node_features); use_h1=1: input = g_h1
__global__ __launch_bounds__(256) void agg_kernel(const float* __restrict__ xin,
                                                  int use_h1, int n_nodes) {
    const float* __restrict__ h = use_h1 ? g_h1 : xin;
    int gw   = (blockIdx.x * blockDim.x + threadIdx.x) >> 5;
    int lane = threadIdx.x & 31;
    if (gw >= n_nodes) return;
    int beg = g_offsets[gw];
    int end = g_offsets[gw + 1];
    float a0 = 0.f, a1 = 0.f;
    for (int base = beg; base < end; base += 32) {
        int myidx = (base + lane < end) ? g_nbr[base + lane] : 0;
        int cnt = min(32, end - base);
        #pragma unroll 4
        for (int j = 0; j < cnt; ++j) {
            int s = __shfl_sync(0xffffffffu, myidx, j);
            float2 v = *(const float2*)(h + (size_t)s * D + lane * 2);
            a0 += v.x;
            a1 += v.y;
        }
    }
    float inv = g_invdeg[gw];
    float2 o;
    o.x = a0 * inv;
    o.y = a1 * inv;
    *(float2*)(g_agg + (size_t)gw * D + lane * 2) = o;
}

// ---------------- layer-1 dense: h1 = tanh(X@Ws1 + b1 + Agg@Wn1) ----------------
// BM=128 rows, BN=64 (full width), 256 threads, per-thread 8x4 tile.
__global__ __launch_bounds__(256) void gemm1_kernel(const float* __restrict__ X,
                                                    const float* __restrict__ Ws,
                                                    const float* __restrict__ b,
                                                    const float* __restrict__ Wn,
                                                    int n_nodes) {
    __shared__ float Ts[128][66];   // tile [m][k], padded
    __shared__ float Wsh[64 * 64];  // [k][n] row-major
    __shared__ float bsh[64];

    int tid = threadIdx.x;
    int tx  = tid & 15;   // n-group: cols tx*4 .. tx*4+3
    int ty  = tid >> 4;   // m-group: rows ty*8 .. ty*8+7
    int m0  = blockIdx.x * 128;

    if (tid < 64) bsh[tid] = b[tid];

    float acc[8][4];
    #pragma unroll
    for (int i = 0; i < 8; ++i)
        #pragma unroll
        for (int j = 0; j < 4; ++j) acc[i][j] = 0.f;

    int mrow = tid >> 4;  // 0..15
    int col4 = tid & 15;  // 0..15 (float4 column)

    for (int phase = 0; phase < 2; ++phase) {
        const float* __restrict__ src = phase ? g_agg : X;
        const float* __restrict__ W   = phase ? Wn : Ws;

        __syncthreads();
        // load 128x64 tile (8 float4 per thread)
        #pragma unroll
        for (int r = 0; r < 8; ++r) {
            int m = r * 16 + mrow;
            float4 v = make_float4(0.f, 0.f, 0.f, 0.f);
            int gm = m0 + m;
            if (gm < n_nodes)
                v = *(const float4*)(src + (size_t)gm * D + col4 * 4);
            Ts[m][col4 * 4 + 0] = v.x;
            Ts[m][col4 * 4 + 1] = v.y;
            Ts[m][col4 * 4 + 2] = v.z;
            Ts[m][col4 * 4 + 3] = v.w;
        }
        // load W 64x64 (4 float4 per thread)
        #pragma unroll
        for (int r = 0; r < 4; ++r) {
            int idx = r * 256 + tid;  // float4 index
            *(float4*)&Wsh[idx * 4] = *(const float4*)(W + (size_t)idx * 4);
        }
        __syncthreads();

        #pragma unroll 4
        for (int k = 0; k < 64; ++k) {
            float4 w = *(const float4*)&Wsh[k * 64 + tx * 4];
            #pragma unroll
            for (int i = 0; i < 8; ++i) {
                float a = Ts[ty * 8 + i][k];
                acc[i][0] += a * w.x;
                acc[i][1] += a * w.y;
                acc[i][2] += a * w.z;
                acc[i][3] += a * w.w;
            }
        }
    }

    // epilogue: bias + tanh, write h1
    float4 bv = *(const float4*)&bsh[tx * 4];
    #pragma unroll
    for (int i = 0; i < 8; ++i) {
        int m = m0 + ty * 8 + i;
        if (m < n_nodes) {
            float4 o;
            o.x = tanhf(acc[i][0] + bv.x);
            o.y = tanhf(acc[i][1] + bv.y);
            o.z = tanhf(acc[i][2] + bv.z);
            o.w = tanhf(acc[i][3] + bv.w);
            *(float4*)(g_h1 + (size_t)m * D + tx * 4) = o;
        }
    }
}

// ---------------- layer-2 dense: out = h1@Ws2 + b2 + Agg2@Wn2 (4 classes) --------
__global__ __launch_bounds__(256) void layer2_kernel(const float* __restrict__ Ws2,
                                                     const float* __restrict__ b2,
                                                     const float* __restrict__ Wn2,
                                                     float* __restrict__ out,
                                                     int n_nodes) {
    __shared__ float ws[256], wn[256], bs[4];
    int t = threadIdx.x;
    if (t < 256) { ws[t] = Ws2[t]; wn[t] = Wn2[t]; }
    if (t < 4) bs[t] = b2[t];
    __syncthreads();

    int n = blockIdx.x * blockDim.x + t;
    if (n >= n_nodes) return;

    float acc0 = bs[0], acc1 = bs[1], acc2 = bs[2], acc3 = bs[3];
    const float4* hp = (const float4*)(g_h1  + (size_t)n * D);
    const float4* ap = (const float4*)(g_agg + (size_t)n * D);
    #pragma unroll
    for (int q = 0; q < 16; ++q) {
        float4 h = hp[q];
        float4 a = ap[q];
        float hv[4] = {h.x, h.y, h.z, h.w};
        float av[4] = {a.x, a.y, a.z, a.w};
        #pragma unroll
        for (int j = 0; j < 4; ++j) {
            int k = q * 4 + j;
            float4 w = *(const float4*)&ws[k * 4];
            float4 v = *(const float4*)&wn[k * 4];
            acc0 += hv[j] * w.x + av[j] * v.x;
            acc1 += hv[j] * w.y + av[j] * v.y;
            acc2 += hv[j] * w.z + av[j] * v.z;
            acc3 += hv[j] * w.w + av[j] * v.w;
        }
    }
    float4 o = make_float4(acc0, acc1, acc2, acc3);
    *(float4*)(out + (size_t)n * 4) = o;
}

// ---------------- launch ----------------
extern "C" void kernel_launch(void* const* d_in, const int* in_sizes, int n_in,
                              void* d_out, int out_size) {
    const float* x    = (const float*)d_in[0];
    const int*   esrc = (const int*)d_in[1];
    const int*   edst = (const int*)d_in[2];
    const float* Ws1  = (const float*)d_in[3];
    const float* b1   = (const float*)d_in[4];
    const float* Wn1  = (const float*)d_in[5];
    const float* Ws2  = (const float*)d_in[6];
    const float* b2   = (const float*)d_in[7];
    const float* Wn2  = (const float*)d_in[8];
    float* out = (float*)d_out;

    int n_nodes = in_sizes[0] / D;
    int n_edges = in_sizes[1];

    // CSR build (dst -> src)
    zero_counts_kernel<<<(n_nodes + 255) / 256, 256>>>(n_nodes);
    hist_kernel<<<(n_edges + 255) / 256, 256>>>(edst, n_edges);
    scan_kernel<<<1, 1024>>>(n_nodes);
    scatter_kernel<<<(n_edges + 255) / 256, 256>>>(esrc, edst, n_edges);

    // layer 1
    int agg_blocks = (n_nodes * 32 + 255) / 256;
    agg_kernel<<<agg_blocks, 256>>>(x, 0, n_nodes);
    gemm1_kernel<<<(n_nodes + 127) / 128, 256>>>(x, Ws1, b1, Wn1, n_nodes);

    // layer 2
    agg_kernel<<<agg_blocks, 256>>>(x, 1, n_nodes);
    layer2_kernel<<<(n_nodes + 255) / 256, 256>>>(Ws2, b2, Wn2, out, n_nodes);
}

// round 2
// speedup vs baseline: 2.6337x; 2.6337x over previous
#include <cuda_runtime.h>
#include <cuda_bf16.h>
#include <cstdint>

#define MAX_NODES 100000
#define MAX_EDGES 1600000
#define D 64
#define MAX_PARTS 512   // >= ceil(MAX_NODES/256)

// ---------------- scratch (device globals) ----------------
__device__ int    g_counts[MAX_NODES + 1];
__device__ int    g_cursor[MAX_NODES + 1];
__device__ int    g_offsets[MAX_NODES + 1];
__device__ float  g_invdeg[MAX_NODES];
__device__ int    g_nbr[MAX_EDGES];
__device__ int    g_part[MAX_PARTS];
__device__ int    g_partoff[MAX_PARTS];
__device__ float  g_agg[(size_t)MAX_NODES * D];   // layer-1 h_neigh (pre-scaled)
__device__ float  g_h1[(size_t)MAX_NODES * D];    // layer-1 activations
__device__ float4 g_z[MAX_NODES];                 // h1 @ Wn2
__device__ float4 g_s[MAX_NODES];                 // h1 @ Ws2 + b2

// ---------------- CSR build ----------------
__global__ void zero_counts_kernel(int n_nodes) {
    int i = blockIdx.x * blockDim.x + threadIdx.x;
    if (i < n_nodes) g_counts[i] = 0;
}

// 4 edges per thread, independent RED chains
__global__ void hist_kernel(const int* __restrict__ edge_dst, int n_edges) {
    int i4 = (blockIdx.x * blockDim.x + threadIdx.x) * 4;
    if (i4 + 4 <= n_edges) {
        int4 d = *(const int4*)(edge_dst + i4);
        atomicAdd(&g_counts[d.x], 1);
        atomicAdd(&g_counts[d.y], 1);
        atomicAdd(&g_counts[d.z], 1);
        atomicAdd(&g_counts[d.w], 1);
    } else {
        for (int i = i4; i < n_edges; ++i) atomicAdd(&g_counts[edge_dst[i]], 1);
    }
}

// block-local exclusive scan of counts -> g_offsets (local), block total -> g_part
__global__ __launch_bounds__(256) void scanA_kernel(int n_nodes) {
    __shared__ int wsum[8];
    int i = blockIdx.x * 256 + threadIdx.x;
    int c = (i < n_nodes) ? g_counts[i] : 0;
    int lane = threadIdx.x & 31, wid = threadIdx.x >> 5;
    int v = c;
    #pragma unroll
    for (int o = 1; o < 32; o <<= 1) {
        int u = __shfl_up_sync(0xffffffffu, v, o);
        if (lane >= o) v += u;
    }
    if (lane == 31) wsum[wid] = v;
    __syncthreads();
    if (wid == 0) {
        int w = (lane < 8) ? wsum[lane] : 0;
        #pragma unroll
        for (int o = 1; o < 8; o <<= 1) {
            int u = __shfl_up_sync(0xffffffffu, w, o);
            if (lane >= o) w += u;
        }
        if (lane < 8) wsum[lane] = w;
    }
    __syncthreads();
    int base = (wid > 0) ? wsum[wid - 1] : 0;
    int incl = v + base;
    if (i < n_nodes) g_offsets[i] = incl - c;  // local exclusive
    if (threadIdx.x == 255) g_part[blockIdx.x] = incl;
}

// single-block scan of partials
__global__ __launch_bounds__(MAX_PARTS) void scanB_kernel(int np) {
    __shared__ int s[MAX_PARTS];
    int t = threadIdx.x;
    int mine = (t < np) ? g_part[t] : 0;
    s[t] = mine;
    __syncthreads();
    for (int o = 1; o < MAX_PARTS; o <<= 1) {
        int v = (t >= o) ? s[t - o] : 0;
        __syncthreads();
        s[t] += v;
        __syncthreads();
    }
    g_partoff[t] = s[t] - mine;  // exclusive
}

// add base, fill cursor/invdeg
__global__ void scanC_kernel(int n_nodes, int n_edges) {
    int i = blockIdx.x * blockDim.x + threadIdx.x;
    if (i < n_nodes) {
        int off = g_offsets[i] + g_partoff[i >> 8];
        g_offsets[i] = off;
        g_cursor[i]  = off;
        g_invdeg[i]  = 1.0f / fmaxf((float)g_counts[i], 1.0f);
    }
    if (i == 0) g_offsets[n_nodes] = n_edges;
}

// 4 edges per thread for ILP
__global__ void scatter_kernel(const int* __restrict__ edge_src,
                               const int* __restrict__ edge_dst, int n_edges) {
    int i4 = (blockIdx.x * blockDim.x + threadIdx.x) * 4;
    if (i4 + 4 <= n_edges) {
        int4 d = *(const int4*)(edge_dst + i4);
        int4 sv = *(const int4*)(edge_src + i4);
        int p0 = atomicAdd(&g_cursor[d.x], 1);
        int p1 = atomicAdd(&g_cursor[d.y], 1);
        int p2 = atomicAdd(&g_cursor[d.z], 1);
        int p3 = atomicAdd(&g_cursor[d.w], 1);
        g_nbr[p0] = sv.x; g_nbr[p1] = sv.y; g_nbr[p2] = sv.z; g_nbr[p3] = sv.w;
    } else {
        for (int i = i4; i < n_edges; ++i) {
            int p = atomicAdd(&g_cursor[edge_dst[i]], 1);
            g_nbr[p] = edge_src[i];
        }
    }
}

// ---------------- layer-1 aggregation: warp/node, 2 neighbors per iter ----------
__global__ __launch_bounds__(256) void agg1_kernel(const float* __restrict__ x,
                                                   int n_nodes) {
    int gw   = (blockIdx.x * blockDim.x + threadIdx.x) >> 5;
    int lane = threadIdx.x & 31;
    if (gw >= n_nodes) return;
    int beg = g_offsets[gw];
    int end = g_offsets[gw + 1];
    int half = lane >> 4;   // 0/1: which neighbor of the pair
    int l16  = lane & 15;   // float4 column group
    float4 acc = make_float4(0.f, 0.f, 0.f, 0.f);
    for (int base = beg; base < end; base += 32) {
        int idx = (base + lane < end) ? g_nbr[base + lane] : 0;
        int cnt = min(32, end - base);
        #pragma unroll 4
        for (int j = 0; j < cnt; j += 2) {
            int take = j + half;
            int s = __shfl_sync(0xffffffffu, idx, (take < 32) ? take : 0);
            if (take < cnt) {
                float4 v = *(const float4*)(x + (size_t)s * D + l16 * 4);
                acc.x += v.x; acc.y += v.y; acc.z += v.z; acc.w += v.w;
            }
        }
    }
    // combine the two half-warps (same columns)
    acc.x += __shfl_xor_sync(0xffffffffu, acc.x, 16);
    acc.y += __shfl_xor_sync(0xffffffffu, acc.y, 16);
    acc.z += __shfl_xor_sync(0xffffffffu, acc.z, 16);
    acc.w += __shfl_xor_sync(0xffffffffu, acc.w, 16);
    if (half == 0) {
        float inv = g_invdeg[gw];
        float4 o = make_float4(acc.x * inv, acc.y * inv, acc.z * inv, acc.w * inv);
        *(float4*)(g_agg + (size_t)gw * D + l16 * 4) = o;
    }
}

// ---------------- layer-1 dense: h1 = tanh(X@Ws1 + b1 + Agg@Wn1) ----------------
__global__ __launch_bounds__(256) void gemm1_kernel(const float* __restrict__ X,
                                                    const float* __restrict__ Ws,
                                                    const float* __restrict__ b,
                                                    const float* __restrict__ Wn,
                                                    int n_nodes) {
    __shared__ float Ts[128][66];
    __shared__ float Wsh[64 * 64];
    __shared__ float bsh[64];

    int tid = threadIdx.x;
    int tx  = tid & 15;
    int ty  = tid >> 4;
    int m0  = blockIdx.x * 128;

    if (tid < 64) bsh[tid] = b[tid];

    float acc[8][4];
    #pragma unroll
    for (int i = 0; i < 8; ++i)
        #pragma unroll
        for (int j = 0; j < 4; ++j) acc[i][j] = 0.f;

    int mrow = tid >> 4;
    int col4 = tid & 15;

    for (int phase = 0; phase < 2; ++phase) {
        const float* __restrict__ src = phase ? g_agg : X;
        const float* __restrict__ W   = phase ? Wn : Ws;

        __syncthreads();
        #pragma unroll
        for (int r = 0; r < 8; ++r) {
            int m = r * 16 + mrow;
            float4 v = make_float4(0.f, 0.f, 0.f, 0.f);
            int gm = m0 + m;
            if (gm < n_nodes)
                v = *(const float4*)(src + (size_t)gm * D + col4 * 4);
            Ts[m][col4 * 4 + 0] = v.x;
            Ts[m][col4 * 4 + 1] = v.y;
            Ts[m][col4 * 4 + 2] = v.z;
            Ts[m][col4 * 4 + 3] = v.w;
        }
        #pragma unroll
        for (int r = 0; r < 4; ++r) {
            int idx = r * 256 + tid;
            *(float4*)&Wsh[idx * 4] = *(const float4*)(W + (size_t)idx * 4);
        }
        __syncthreads();

        #pragma unroll 4
        for (int k = 0; k < 64; ++k) {
            float4 w = *(const float4*)&Wsh[k * 64 + tx * 4];
            #pragma unroll
            for (int i = 0; i < 8; ++i) {
                float a = Ts[ty * 8 + i][k];
                acc[i][0] += a * w.x;
                acc[i][1] += a * w.y;
                acc[i][2] += a * w.z;
                acc[i][3] += a * w.w;
            }
        }
    }

    float4 bv = *(const float4*)&bsh[tx * 4];
    #pragma unroll
    for (int i = 0; i < 8; ++i) {
        int m = m0 + ty * 8 + i;
        if (m < n_nodes) {
            float4 o;
            o.x = tanhf(acc[i][0] + bv.x);
            o.y = tanhf(acc[i][1] + bv.y);
            o.z = tanhf(acc[i][2] + bv.z);
            o.w = tanhf(acc[i][3] + bv.w);
            *(float4*)(g_h1 + (size_t)m * D + tx * 4) = o;
        }
    }
}

// ---------------- layer-2 projections: z = h1@Wn2, s = h1@Ws2 + b2 --------------
__global__ __launch_bounds__(256) void zproj_kernel(const float* __restrict__ Ws2,
                                                    const float* __restrict__ b2,
                                                    const float* __restrict__ Wn2,
                                                    int n_nodes) {
    __shared__ float ws[256], wn[256], bs[4];
    int t = threadIdx.x;
    ws[t] = Ws2[t];
    wn[t] = Wn2[t];
    if (t < 4) bs[t] = b2[t];
    __syncthreads();

    int n = blockIdx.x * blockDim.x + t;
    if (n >= n_nodes) return;

    float s0 = bs[0], s1 = bs[1], s2 = bs[2], s3 = bs[3];
    float z0 = 0.f, z1 = 0.f, z2 = 0.f, z3 = 0.f;
    const float4* hp = (const float4*)(g_h1 + (size_t)n * D);
    #pragma unroll
    for (int q = 0; q < 16; ++q) {
        float4 h = hp[q];
        float hv[4] = {h.x, h.y, h.z, h.w};
        #pragma unroll
        for (int j = 0; j < 4; ++j) {
            int k = q * 4 + j;
            float4 w = *(const float4*)&ws[k * 4];
            float4 v = *(const float4*)&wn[k * 4];
            s0 += hv[j] * w.x; s1 += hv[j] * w.y; s2 += hv[j] * w.z; s3 += hv[j] * w.w;
            z0 += hv[j] * v.x; z1 += hv[j] * v.y; z2 += hv[j] * v.z; z3 += hv[j] * v.w;
        }
    }
    g_s[n] = make_float4(s0, s1, s2, s3);
    g_z[n] = make_float4(z0, z1, z2, z3);
}

// ---------------- layer-2 aggregation over z (4-wide) + finalize ----------------
__global__ __launch_bounds__(256) void agg2_kernel(float* __restrict__ out,
                                                   int n_nodes) {
    int n = blockIdx.x * blockDim.x + threadIdx.x;
    if (n >= n_nodes) return;
    int beg = g_offsets[n];
    int end = g_offsets[n + 1];
    float4 acc = make_float4(0.f, 0.f, 0.f, 0.f);
    int e = beg;
    for (; e + 4 <= end; e += 4) {
        int i0 = g_nbr[e], i1 = g_nbr[e + 1], i2 = g_nbr[e + 2], i3 = g_nbr[e + 3];
        float4 a = g_z[i0], b = g_z[i1], c = g_z[i2], d = g_z[i3];
        acc.x += a.x + b.x + c.x + d.x;
        acc.y += a.y + b.y + c.y + d.y;
        acc.z += a.z + b.z + c.z + d.z;
        acc.w += a.w + b.w + c.w + d.w;
    }
    for (; e < end; ++e) {
        float4 a = g_z[g_nbr[e]];
        acc.x += a.x; acc.y += a.y; acc.z += a.z; acc.w += a.w;
    }
    float inv = g_invdeg[n];
    float4 s = g_s[n];
    float4 o = make_float4(s.x + acc.x * inv, s.y + acc.y * inv,
                           s.z + acc.z * inv, s.w + acc.w * inv);
    *(float4*)(out + (size_t)n * 4) = o;
}

// ---------------- launch ----------------
extern "C" void kernel_launch(void* const* d_in, const int* in_sizes, int n_in,
                              void* d_out, int out_size) {
    const float* x    = (const float*)d_in[0];
    const int*   esrc = (const int*)d_in[1];
    const int*   edst = (const int*)d_in[2];
    const float* Ws1  = (const float*)d_in[3];
    const float* b1   = (const float*)d_in[4];
    const float* Wn1  = (const float*)d_in[5];
    const float* Ws2  = (const float*)d_in[6];
    const float* b2   = (const float*)d_in[7];
    const float* Wn2  = (const float*)d_in[8];
    float* out = (float*)d_out;

    int n_nodes = in_sizes[0] / D;
    int n_edges = in_sizes[1];
    int np = (n_nodes + 255) / 256;
    int e4_blocks = ((n_edges + 3) / 4 + 255) / 256;

    // CSR build (dst -> src)
    zero_counts_kernel<<<(n_nodes + 255) / 256, 256>>>(n_nodes);
    hist_kernel<<<e4_blocks, 256>>>(edst, n_edges);
    scanA_kernel<<<np, 256>>>(n_nodes);
    scanB_kernel<<<1, MAX_PARTS>>>(np);
    scanC_kernel<<<(n_nodes + 255) / 256, 256>>>(n_nodes, n_edges);
    scatter_kernel<<<e4_blocks, 256>>>(esrc, edst, n_edges);

    // layer 1
    int agg_blocks = (n_nodes * 32 + 255) / 256;
    agg1_kernel<<<agg_blocks, 256>>>(x, n_nodes);
    gemm1_kernel<<<(n_nodes + 127) / 128, 256>>>(x, Ws1, b1, Wn1, n_nodes);

    // layer 2 (project-then-aggregate: Agg(h1)@W == Agg(h1@W))
    zproj_kernel<<<(n_nodes + 255) / 256, 256>>>(Ws2, b2, Wn2, n_nodes);
    agg2_kernel<<<(n_nodes + 255) / 256, 256>>>(out, n_nodes);
}